// round 14
// baseline (speedup 1.0000x reference)
#include <cuda_runtime.h>
#include <cuda_bf16.h>
#include <math.h>
#include <stdint.h>

#define BB 64
#define TT 256
#define HH 1024
#define VV 128
#define NG 4096   // 4*H

// ---------------- device scratch (no allocations allowed) ----------------
__device__ float g_gx[BB * TT * NG];              // gate pre-activations, T-major [T][B][4H]
__device__ __nv_bfloat16 g_y0b[BB * TT * HH];     // layer-0 output big
__device__ __nv_bfloat16 g_y0s[BB * TT * HH];     // layer-0 output small
__device__ __nv_bfloat16 g_y1b[BB * TT * HH];     // layer-1 output big
__device__ __nv_bfloat16 g_y1s[BB * TT * HH];     // layer-1 output small
__device__ __nv_bfloat16 g_hsb[2][BB * HH];       // hidden state big, double-buffered
__device__ __nv_bfloat16 g_hss[2][BB * HH];       // hidden state small, double-buffered
__device__ float g_c[BB * HH];                    // cell state (CTA-private cells)
__device__ float g_part[2][8 * BB * NG];          // k-split partials, double-buffered
__device__ __nv_bfloat16 g_wAb[NG * HH];          // W_ih / fc_W big
__device__ __nv_bfloat16 g_wAs[NG * HH];          // W_ih / fc_W small
__device__ __nv_bfloat16 g_embb[VV * HH];         // embedding big
__device__ __nv_bfloat16 g_embs[VV * HH];         // embedding small
__device__ unsigned g_barc;                       // global barrier arrival counter (init only)
__device__ volatile unsigned g_barsf[16 * 8];     // 16 release flags, 32B-spaced
__device__ volatile unsigned g_cnt2[8 * 8];       // per-ks-group h-ready counters (monotonic)
__device__ volatile unsigned g_cntcs[16 * 8];     // per-col-tile partials-ready counters (monotonic)

// ---------------- helpers ----------------
__device__ __forceinline__ void bf16_split(float x, __nv_bfloat16& b, __nv_bfloat16& s) {
    b = __float2bfloat16(x);
    s = __float2bfloat16(x - __bfloat162float(b));
}

__device__ __forceinline__ uint32_t pack_bf2(__nv_bfloat16 lo, __nv_bfloat16 hi) {
    __nv_bfloat162 t = __halves2bfloat162(lo, hi);
    return *reinterpret_cast<uint32_t*>(&t);
}

__device__ __forceinline__ uint32_t sw64(uint32_t x) {      // SW64 swizzle (64-B rows)
    return x ^ ((x >> 3) & 0x30);
}

__device__ __forceinline__ uint32_t smem_u32(const void* p) {
    uint32_t a;
    asm("{ .reg .u64 t; cvta.to.shared.u64 t, %1; cvt.u32.u64 %0, t; }" : "=r"(a) : "l"(p));
    return a;
}

__device__ __forceinline__ void mma_bf16(float* d, const uint32_t* a, const uint32_t* b) {
    asm volatile(
        "mma.sync.aligned.m16n8k16.row.col.f32.bf16.bf16.f32 "
        "{%0,%1,%2,%3}, {%4,%5,%6,%7}, {%8,%9}, {%0,%1,%2,%3};\n"
        : "+f"(d[0]), "+f"(d[1]), "+f"(d[2]), "+f"(d[3])
        : "r"(a[0]), "r"(a[1]), "r"(a[2]), "r"(a[3]), "r"(b[0]), "r"(b[1]));
}

__device__ __forceinline__ void ldsm4(uint32_t* r, uint32_t addr) {
    asm volatile(
        "ldmatrix.sync.aligned.m8n8.x4.shared.b16 {%0,%1,%2,%3}, [%4];"
        : "=r"(r[0]), "=r"(r[1]), "=r"(r[2]), "=r"(r[3]) : "r"(addr));
}

__device__ __forceinline__ float rcp_approx(float d) {
    float r;
    asm("rcp.approx.f32 %0, %1;" : "=f"(r) : "f"(d));
    return r;
}

__device__ __forceinline__ float fast_sigmoid(float x) {   // 1/(1+e^-x)
    const float a = fmaxf(fminf(-x, 40.f), -40.f);
    return rcp_approx(1.f + __expf(a));
}

__device__ __forceinline__ float fast_tanh(float x) {      // 1 - 2/(e^{2x}+1)
    const float a = fmaxf(fminf(2.f * x, 40.f), -40.f);
    return 1.f - 2.f * rcp_approx(__expf(a) + 1.f);
}

// ---------------- global barrier (init only) ----------------
__device__ __forceinline__ void grid_bar(unsigned* sense) {
    __syncthreads();
    if (threadIdx.x == 0) {
        unsigned s = *sense ^ 1u;
        *sense = s;
        __threadfence();                       // release
        unsigned prev = atomicAdd(&g_barc, 1u);
        if (prev == gridDim.x - 1) {
            g_barc = 0u;
            __threadfence();
            #pragma unroll
            for (int i = 0; i < 16; i++) g_barsf[i * 8] = s;
        } else {
            volatile unsigned* f = &g_barsf[(blockIdx.x >> 3) * 8];
            while (*f != s) { }
            __threadfence();                   // acquire
        }
    }
    __syncthreads();
}

// ---------------- fp32 -> (bf16 big, bf16 small) split ----------------
__global__ void cvt_split_kernel(const float* __restrict__ src,
                                 __nv_bfloat16* __restrict__ dstb,
                                 __nv_bfloat16* __restrict__ dsts, int n) {
    for (int i = blockIdx.x * blockDim.x + threadIdx.x; i < n; i += gridDim.x * blockDim.x) {
        __nv_bfloat16 b, s;
        bf16_split(src[i], b, s);
        dstb[i] = b;
        dsts[i] = s;
    }
}

// ---------------- ldmatrix split-bf16 SGEMM (unchanged from R13) ----------------
template <bool GATHER, bool TMAJOR>
__global__ __launch_bounds__(256, 2)
void sgemm_ldsm(const __nv_bfloat16* __restrict__ Ab, const __nv_bfloat16* __restrict__ As_,
                const int* __restrict__ tok,
                const __nv_bfloat16* __restrict__ Wb, const __nv_bfloat16* __restrict__ Ws_,
                const float* __restrict__ bias,
                float* __restrict__ C, int M, int N, int K)
{
    extern __shared__ uint8_t smg_raw[];
    uint8_t* smg = (uint8_t*)(((uintptr_t)smg_raw + 127) & ~(uintptr_t)127);
    const uint32_t smb = smem_u32(smg);

    const int tid = threadIdx.x;
    const int warp = tid >> 5;
    const int lane = tid & 31;
    const int m0 = blockIdx.y * 128;
    const int n0 = blockIdx.x * 128;
    const int mbase = (warp >> 2) * 64;
    const int nbase = (warp & 3) * 32;
    const int r = lane & 3;
    const int q = lane >> 2;

    uint32_t offA[4], offB[2];
    {
        const int ar = (lane & 7) + 8 * ((lane >> 3) & 1);
        const int abyt = ((lane >> 4) & 1) * 16;
        #pragma unroll
        for (int mf = 0; mf < 4; mf++)
            offA[mf] = sw64((mbase + mf * 16 + ar) * 64 + abyt);
        const int br = (lane & 7) + 8 * ((lane >> 4) & 1);
        const int bbyt = ((lane >> 3) & 1) * 16;
        #pragma unroll
        for (int n2 = 0; n2 < 2; n2++)
            offB[n2] = sw64((nbase + n2 * 16 + br) * 64 + bbyt);
    }

    const int srow = tid >> 1;
    const int so0i = srow * 64 + (tid & 1) * 32;
    const uint32_t so0 = sw64(so0i);
    const uint32_t so1 = sw64(so0i + 16);

    size_t aoff;
    if (GATHER) aoff = (size_t)tok[m0 + srow] * K;
    else        aoff = (size_t)(m0 + srow) * K;
    const __nv_bfloat16* arb = Ab  + aoff + (tid & 1) * 16;
    const __nv_bfloat16* ars = As_ + aoff + (tid & 1) * 16;
    const __nv_bfloat16* wrb = Wb  + (size_t)(n0 + srow) * K + (tid & 1) * 16;
    const __nv_bfloat16* wrs = Ws_ + (size_t)(n0 + srow) * K + (tid & 1) * 16;

    float acc[4][4][4];
    #pragma unroll
    for (int mf = 0; mf < 4; mf++)
        #pragma unroll
        for (int nf = 0; nf < 4; nf++)
            #pragma unroll
            for (int i = 0; i < 4; i++) acc[mf][nf][i] = 0.f;

    uint4 pab0 = *(const uint4*)(arb);
    uint4 pab1 = *(const uint4*)(arb + 8);
    uint4 pas0 = *(const uint4*)(ars);
    uint4 pas1 = *(const uint4*)(ars + 8);
    uint4 pwb0 = *(const uint4*)(wrb);
    uint4 pwb1 = *(const uint4*)(wrb + 8);
    uint4 pws0 = *(const uint4*)(wrs);
    uint4 pws1 = *(const uint4*)(wrs + 8);

    const int nslice = K / 32;
    for (int s = 0; s < nslice; s++) {
        const uint32_t bo = (uint32_t)(s & 1) * 32768u;
        *(uint4*)(smg + bo + so0)         = pab0;
        *(uint4*)(smg + bo + so1)         = pab1;
        *(uint4*)(smg + bo + 8192 + so0)  = pas0;
        *(uint4*)(smg + bo + 8192 + so1)  = pas1;
        *(uint4*)(smg + bo + 16384 + so0) = pwb0;
        *(uint4*)(smg + bo + 16384 + so1) = pwb1;
        *(uint4*)(smg + bo + 24576 + so0) = pws0;
        *(uint4*)(smg + bo + 24576 + so1) = pws1;
        if (s + 1 < nslice) {
            const int k0 = (s + 1) * 32;
            pab0 = *(const uint4*)(arb + k0);
            pab1 = *(const uint4*)(arb + k0 + 8);
            pas0 = *(const uint4*)(ars + k0);
            pas1 = *(const uint4*)(ars + k0 + 8);
            pwb0 = *(const uint4*)(wrb + k0);
            pwb1 = *(const uint4*)(wrb + k0 + 8);
            pws0 = *(const uint4*)(wrs + k0);
            pws1 = *(const uint4*)(wrs + k0 + 8);
        }
        __syncthreads();

        const uint32_t bAb = smb + bo;
        const uint32_t bAs = bAb + 8192;
        const uint32_t bBb = bAb + 16384;
        const uint32_t bBs = bAb + 24576;
        #pragma unroll
        for (int kc = 0; kc < 2; kc++) {
            const uint32_t kcb = (uint32_t)kc * 32u;
            uint32_t abf[4][4], bbf[2][4];
            #pragma unroll
            for (int mf = 0; mf < 4; mf++) ldsm4(abf[mf], bAb + (offA[mf] ^ kcb));
            #pragma unroll
            for (int n2 = 0; n2 < 2; n2++) ldsm4(bbf[n2], bBb + (offB[n2] ^ kcb));
            #pragma unroll
            for (int mf = 0; mf < 4; mf++)
                #pragma unroll
                for (int nf = 0; nf < 4; nf++)
                    mma_bf16(acc[mf][nf], abf[mf], &bbf[nf >> 1][(nf & 1) * 2]);
            {
                uint32_t bsf[2][4];
                #pragma unroll
                for (int n2 = 0; n2 < 2; n2++) ldsm4(bsf[n2], bBs + (offB[n2] ^ kcb));
                #pragma unroll
                for (int mf = 0; mf < 4; mf++)
                    #pragma unroll
                    for (int nf = 0; nf < 4; nf++)
                        mma_bf16(acc[mf][nf], abf[mf], &bsf[nf >> 1][(nf & 1) * 2]);
            }
            {
                uint32_t asf[4][4];
                #pragma unroll
                for (int mf = 0; mf < 4; mf++) ldsm4(asf[mf], bAs + (offA[mf] ^ kcb));
                #pragma unroll
                for (int mf = 0; mf < 4; mf++)
                    #pragma unroll
                    for (int nf = 0; nf < 4; nf++)
                        mma_bf16(acc[mf][nf], asf[mf], &bbf[nf >> 1][(nf & 1) * 2]);
            }
        }
    }

    #pragma unroll
    for (int nf = 0; nf < 4; nf++) {
        const int n = n0 + nbase + nf * 8 + 2 * r;
        const float b0v = bias[n];
        const float b1v = bias[n + 1];
        #pragma unroll
        for (int mf = 0; mf < 4; mf++) {
            const int m = m0 + mbase + mf * 16 + q;
            size_t row0, row1;
            if (TMAJOR) {
                row0 = (size_t)((m % TT) * BB + m / TT);
                const int m8 = m + 8;
                row1 = (size_t)((m8 % TT) * BB + m8 / TT);
            } else {
                row0 = (size_t)m;
                row1 = (size_t)(m + 8);
            }
            float2 o0 = {acc[mf][nf][0] + b0v, acc[mf][nf][1] + b1v};
            float2 o1 = {acc[mf][nf][2] + b0v, acc[mf][nf][3] + b1v};
            *(float2*)(C + row0 * N + n) = o0;
            *(float2*)(C + row1 * N + n) = o1;
        }
    }
}

// ---------------- persistent LSTM layer kernel (LDSM phase A, pre-split h) ----------------
// grid = 128 CTAs (16 col tiles x 8 k-splits), 256 threads.
// W stationary in 128 KB dyn smem as [part][ktile(4)][col(256)][64B] SW64.
// h staged per step into [part][ktile(4)][row(64)][64B] SW64 (pure copy, no cvt).
// Sync structure identical to R12/R13 (dependency-scoped counters).
__global__ __launch_bounds__(256, 1)
void lstm_layer(const float* __restrict__ gx, const float* __restrict__ Whh,
                const float* __restrict__ h0, const float* __restrict__ c0,
                __nv_bfloat16* __restrict__ yb, __nv_bfloat16* __restrict__ ys)
{
    extern __shared__ uint8_t wsm[];          // [2 parts][4 kt][256 col][64B] = 128 KB
    __shared__ uint8_t hb_sm[16384];          // [4 kt][64 row][64B]
    __shared__ uint8_t hs_sm[16384];

    const int tid = threadIdx.x;
    const int bid = blockIdx.x;       // 0..127
    const int cs  = bid & 15;
    const int ks  = bid >> 4;
    const int col0 = cs * 256;
    const int gtid = bid * 256 + tid;

    const int warp = tid >> 5;
    const int lane = tid & 31;
    const int r = lane & 3;
    const int q = lane >> 2;
    const int nbase = warp * 32;

    const uint32_t wsmb = smem_u32(wsm);
    const uint32_t hbb  = smem_u32(hb_sm);
    const uint32_t hsb_ = smem_u32(hs_sm);

    unsigned sense = g_barsf[(bid >> 3) * 8];

    // ---- one-time W slice load + split into SW64 ktile layout ----
    {
        const float* wsrc = Whh + (size_t)(col0 + tid) * HH + ks * 128;
        #pragma unroll
        for (int g = 0; g < 16; g++) {           // 8 k per iteration
            float4 v0 = *(const float4*)(wsrc + 8 * g);
            float4 v1 = *(const float4*)(wsrc + 8 * g + 4);
            const float wv[8] = {v0.x, v0.y, v0.z, v0.w, v1.x, v1.y, v1.z, v1.w};
            uint32_t pb[4], ps[4];
            #pragma unroll
            for (int p = 0; p < 4; p++) {
                __nv_bfloat16 b0, s0, b1, s1;
                bf16_split(wv[2 * p], b0, s0);
                bf16_split(wv[2 * p + 1], b1, s1);
                pb[p] = pack_bf2(b0, b1);
                ps[p] = pack_bf2(s0, s1);
            }
            const uint32_t kt = (uint32_t)(g >> 2);
            const uint32_t base = sw64((uint32_t)tid * 64u + (uint32_t)((16 * g) & 63));
            const uint32_t off = kt * 16384u + base;
            *(uint4*)(wsm + off)           = *(uint4*)pb;
            *(uint4*)(wsm + 65536u + off)  = *(uint4*)ps;
        }
    }

    // init state: split h0 into hsplit[0]; copy c; reset counters
    for (int i = gtid; i < BB * HH; i += 128 * 256) {
        __nv_bfloat16 b, s;
        bf16_split(h0[i], b, s);
        g_hsb[0][i] = b;
        g_hss[0][i] = s;
        g_c[i] = c0[i];
    }
    if (tid == 0 && bid < 8)  *((volatile unsigned*)&g_cnt2[bid * 8])  = 0u;
    if (tid == 0 && bid < 16) *((volatile unsigned*)&g_cntcs[bid * 8]) = 0u;
    grid_bar(&sense);

    // fragment offsets (validated lane mapping from sgemm_ldsm)
    uint32_t offA[4], offBw[2];
    {
        const int ar = (lane & 7) + 8 * ((lane >> 3) & 1);
        const int abyt = ((lane >> 4) & 1) * 16;
        #pragma unroll
        for (int mf = 0; mf < 4; mf++)
            offA[mf] = sw64((mf * 16 + ar) * 64 + abyt);
        const int br = (lane & 7) + 8 * ((lane >> 4) & 1);
        const int bbyt = ((lane >> 3) & 1) * 16;
        #pragma unroll
        for (int n2 = 0; n2 < 2; n2++)
            offBw[n2] = sw64((nbase + n2 * 16 + br) * 64 + bbyt);
    }

    // h staging indices: row = tid>>2 (0..63), ktile = tid&3 (32 k = 64 B each)
    const int hrow = tid >> 2;
    const int hkt  = tid & 3;
    const size_t hgoff = (size_t)hrow * HH + ks * 128 + hkt * 32;
    uint32_t hsts[4];
    #pragma unroll
    for (int j = 0; j < 4; j++)
        hsts[j] = (uint32_t)hkt * 4096u + sw64((uint32_t)hrow * 64u + (uint32_t)j * 16u);

    // phase-B ks-local ownership
    const int pb_b  = 4 * cs + (tid >> 6);
    const int pb_j  = 128 * ks + (tid & 63) * 2;
    const int cellp = pb_b * 1024 + pb_j;
    const int src_tile0 = ks >> 1;

    for (int t = 0; t < TT; t++) {
        const int par = t & 1;
        float* partp = g_part[par];

        // ---- group wait: own ks-group's h for this step is ready ----
        if (t > 0) {
            if (tid == 0) {
                const unsigned need = 16u * (unsigned)t;
                volatile unsigned* cp = &g_cnt2[ks * 8];
                while (*cp < need) { }
                __threadfence();               // acquire
            }
            __syncthreads();
        }

        // ---- stage h slice: pure 64-B copies, no conversions, one sync ----
        {
            const uint4* gb = (const uint4*)(g_hsb[par] + hgoff);
            const uint4* gs = (const uint4*)(g_hss[par] + hgoff);
            uint4 vb0 = gb[0], vb1 = gb[1], vb2 = gb[2], vb3 = gb[3];
            uint4 vs0 = gs[0], vs1 = gs[1], vs2 = gs[2], vs3 = gs[3];
            *(uint4*)(hb_sm + hsts[0]) = vb0;
            *(uint4*)(hb_sm + hsts[1]) = vb1;
            *(uint4*)(hb_sm + hsts[2]) = vb2;
            *(uint4*)(hb_sm + hsts[3]) = vb3;
            *(uint4*)(hs_sm + hsts[0]) = vs0;
            *(uint4*)(hs_sm + hsts[1]) = vs1;
            *(uint4*)(hs_sm + hsts[2]) = vs2;
            *(uint4*)(hs_sm + hsts[3]) = vs3;
        }
        __syncthreads();

        float acc[4][4][4];
        #pragma unroll
        for (int mf = 0; mf < 4; mf++)
            #pragma unroll
            for (int nf = 0; nf < 4; nf++)
                #pragma unroll
                for (int i = 0; i < 4; i++) acc[mf][nf][i] = 0.f;

        // ---- 8 chunks of 16 k: LDSM fragments + 48 mma each ----
        #pragma unroll
        for (int c = 0; c < 8; c++) {
            const uint32_t ka  = (uint32_t)(c >> 1) * 4096u;
            const uint32_t kw  = (uint32_t)(c >> 1) * 16384u;
            const uint32_t kcb = (uint32_t)(c & 1) * 32u;
            uint32_t abf[4][4], bbf[2][4];
            #pragma unroll
            for (int mf = 0; mf < 4; mf++) ldsm4(abf[mf], hbb + ka + (offA[mf] ^ kcb));
            #pragma unroll
            for (int n2 = 0; n2 < 2; n2++) ldsm4(bbf[n2], wsmb + kw + (offBw[n2] ^ kcb));
            #pragma unroll
            for (int mf = 0; mf < 4; mf++)
                #pragma unroll
                for (int nf = 0; nf < 4; nf++)
                    mma_bf16(acc[mf][nf], abf[mf], &bbf[nf >> 1][(nf & 1) * 2]);
            {
                uint32_t bsf[2][4];
                #pragma unroll
                for (int n2 = 0; n2 < 2; n2++) ldsm4(bsf[n2], wsmb + 65536u + kw + (offBw[n2] ^ kcb));
                #pragma unroll
                for (int mf = 0; mf < 4; mf++)
                    #pragma unroll
                    for (int nf = 0; nf < 4; nf++)
                        mma_bf16(acc[mf][nf], abf[mf], &bsf[nf >> 1][(nf & 1) * 2]);
            }
            {
                uint32_t asf[4][4];
                #pragma unroll
                for (int mf = 0; mf < 4; mf++) ldsm4(asf[mf], hsb_ + ka + (offA[mf] ^ kcb));
                #pragma unroll
                for (int mf = 0; mf < 4; mf++)
                    #pragma unroll
                    for (int nf = 0; nf < 4; nf++)
                        mma_bf16(acc[mf][nf], asf[mf], &bbf[nf >> 1][(nf & 1) * 2]);
            }
        }

        // write partials P[par][ks][b][col]  (same acc mapping as before)
        #pragma unroll
        for (int nf = 0; nf < 4; nf++) {
            const int col = col0 + nbase + nf * 8 + 2 * r;
            #pragma unroll
            for (int mf = 0; mf < 4; mf++) {
                const int b = mf * 16 + q;
                float2 o0 = {acc[mf][nf][0], acc[mf][nf][1]};
                float2 o1 = {acc[mf][nf][2], acc[mf][nf][3]};
                *(float2*)(&partp[((size_t)ks * BB + b) * NG + col])     = o0;
                *(float2*)(&partp[((size_t)ks * BB + b + 8) * NG + col]) = o1;
            }
        }

        // ---- prefetch gx[t] and c ----
        const float* gr = gx + (size_t)t * BB * NG + (size_t)pb_b * NG + pb_j;
        const float2 xg0 = *(const float2*)(gr);
        const float2 xg1 = *(const float2*)(gr + 1024);
        const float2 xg2 = *(const float2*)(gr + 2048);
        const float2 xg3 = *(const float2*)(gr + 3072);
        float2 cv = *(const float2*)(&g_c[cellp]);

        // ---- signal own partials for step t ----
        __syncthreads();
        if (tid == 0) {
            __threadfence();                   // release partial writes
            atomicAdd((unsigned*)&g_cntcs[cs * 8], 1u);
        }

        // ---- wait: the 4 source col tiles' partials ready ----
        if (tid < 4) {
            const unsigned need = 8u * (unsigned)(t + 1);
            volatile unsigned* cp = &g_cntcs[(src_tile0 + 4 * tid) * 8];
            while (*cp < need) { }
            __threadfence();                   // acquire
        }
        __syncthreads();

        // ---- Phase B ----
        {
            float2 gi = xg0, gf = xg1, gg = xg2, go = xg3;
            #pragma unroll
            for (int s = 0; s < 8; s++) {
                const float* pp = &partp[((size_t)s * BB + pb_b) * NG + pb_j];
                const float2 p0 = *(const float2*)(pp);
                const float2 p1 = *(const float2*)(pp + 1024);
                const float2 p2 = *(const float2*)(pp + 2048);
                const float2 p3 = *(const float2*)(pp + 3072);
                gi.x += p0.x; gi.y += p0.y;
                gf.x += p1.x; gf.y += p1.y;
                gg.x += p2.x; gg.y += p2.y;
                go.x += p3.x; go.y += p3.y;
            }

            const float si0 = fast_sigmoid(gi.x);
            const float si1 = fast_sigmoid(gi.y);
            const float sf0 = fast_sigmoid(gf.x);
            const float sf1 = fast_sigmoid(gf.y);
            const float so0 = fast_sigmoid(go.x);
            const float so1 = fast_sigmoid(go.y);
            cv.x = sf0 * cv.x + si0 * fast_tanh(gg.x);
            cv.y = sf1 * cv.y + si1 * fast_tanh(gg.y);
            const float hv0 = so0 * fast_tanh(cv.x);
            const float hv1 = so1 * fast_tanh(cv.y);
            *(float2*)(&g_c[cellp]) = cv;

            __nv_bfloat16 hb0, hs0, hb1, hs1;
            bf16_split(hv0, hb0, hs0);
            bf16_split(hv1, hb1, hs1);
            const uint32_t pkb = pack_bf2(hb0, hb1);
            const uint32_t pks = pack_bf2(hs0, hs1);
            *(uint32_t*)(&g_hsb[par ^ 1][cellp]) = pkb;   // h for next step (pre-split)
            *(uint32_t*)(&g_hss[par ^ 1][cellp]) = pks;
            const size_t yi = ((size_t)pb_b * TT + t) * HH + pb_j;
            *(uint32_t*)(yb + yi) = pkb;
            *(uint32_t*)(ys + yi) = pks;
        }

        // ---- signal own group's h contribution for step t+1 ----
        __syncthreads();
        if (tid == 0) {
            __threadfence();                   // release h writes
            atomicAdd((unsigned*)&g_cnt2[ks * 8], 1u);
        }
    }
}

// ---------------- launch ----------------
extern "C" void kernel_launch(void* const* d_in, const int* in_sizes, int n_in,
                              void* d_out, int out_size)
{
    const int*   x    = (const int*)  d_in[0];
    const float* emb  = (const float*)d_in[1];
    const float* Wih0 = (const float*)d_in[2];
    const float* Whh0 = (const float*)d_in[3];
    const float* b0   = (const float*)d_in[4];
    const float* Wih1 = (const float*)d_in[5];
    const float* Whh1 = (const float*)d_in[6];
    const float* b1   = (const float*)d_in[7];
    const float* fcW  = (const float*)d_in[8];
    const float* fcb  = (const float*)d_in[9];
    const float* h0   = (const float*)d_in[10];
    const float* c0   = (const float*)d_in[11];
    float* out = (float*)d_out;

    float *gx;
    __nv_bfloat16 *y0b, *y0s, *y1b, *y1s, *wAb, *wAs, *embb, *embs;
    cudaGetSymbolAddress((void**)&gx,   g_gx);
    cudaGetSymbolAddress((void**)&y0b,  g_y0b);
    cudaGetSymbolAddress((void**)&y0s,  g_y0s);
    cudaGetSymbolAddress((void**)&y1b,  g_y1b);
    cudaGetSymbolAddress((void**)&y1s,  g_y1s);
    cudaGetSymbolAddress((void**)&wAb,  g_wAb);
    cudaGetSymbolAddress((void**)&wAs,  g_wAs);
    cudaGetSymbolAddress((void**)&embb, g_embb);
    cudaGetSymbolAddress((void**)&embs, g_embs);

    const int LSTM_SMEM = 131072;   // 128 KB dynamic (W, both parts)
    cudaFuncSetAttribute(lstm_layer, cudaFuncAttributeMaxDynamicSharedMemorySize, LSTM_SMEM);

    const int SG_SMEM = 65536 + 128;
    cudaFuncSetAttribute(sgemm_ldsm<true,  true>,  cudaFuncAttributeMaxDynamicSharedMemorySize, SG_SMEM);
    cudaFuncSetAttribute(sgemm_ldsm<false, true>,  cudaFuncAttributeMaxDynamicSharedMemorySize, SG_SMEM);
    cudaFuncSetAttribute(sgemm_ldsm<false, false>, cudaFuncAttributeMaxDynamicSharedMemorySize, SG_SMEM);

    const int M = BB * TT;  // 16384

    cvt_split_kernel<<<512, 256>>>(emb, embb, embs, VV * HH);
    cvt_split_kernel<<<4096, 256>>>(Wih0, wAb, wAs, NG * HH);

    sgemm_ldsm<true, true><<<dim3(NG / 128, M / 128), 256, SG_SMEM>>>(
        embb, embs, x, wAb, wAs, b0, gx, M, NG, HH);
    lstm_layer<<<128, 256, LSTM_SMEM>>>(gx, Whh0, h0, c0, y0b, y0s);

    cvt_split_kernel<<<4096, 256>>>(Wih1, wAb, wAs, NG * HH);

    sgemm_ldsm<false, true><<<dim3(NG / 128, M / 128), 256, SG_SMEM>>>(
        y0b, y0s, nullptr, wAb, wAs, b1, gx, M, NG, HH);
    lstm_layer<<<128, 256, LSTM_SMEM>>>(gx, Whh1, h0 + BB * HH, c0 + BB * HH, y1b, y1s);

    cvt_split_kernel<<<1024, 256>>>(fcW, wAb, wAs, VV * HH);
    sgemm_ldsm<false, false><<<dim3(VV / 128, M / 128), 256, SG_SMEM>>>(
        y1b, y1s, nullptr, wAb, wAs, fcb, out, M, VV, HH);
}